// round 12
// baseline (speedup 1.0000x reference)
#include <cuda_runtime.h>
#include <cstdint>

// Scatter-add message passing: out[dst] += x[src]
// x: [N, 64] fp32; edge_index: [2, E], int32 or int64 (detected in-kernel).
//
// R12 = R11 with gathers reverted from ld.global.cg to __ldg (default L1
// caching). R11 isolated .cg as a 1.8us kernel regression: src rows have
// ~16x mean reuse (E/N), so L1 caching of x pays. Kept from R11:
//  - in-kernel dtype detect (8 broadcast loads of odd int32 slots)
//  - cudaMemsetAsync zeroing (driver memset node, no kernel launch)
//  - R4/R8 body: MLP=4, 16 lanes/edge-quad, full occupancy.

__device__ __forceinline__ void red_v4(float* out, int dst, int c, float4 v) {
    float4* op = (float4*)(out + (size_t)dst * 64) + c;
    asm volatile("red.global.add.v4.f32 [%0], {%1, %2, %3, %4};"
                 :: "l"(op), "f"(v.x), "f"(v.y), "f"(v.z), "f"(v.w)
                 : "memory");
}

__global__ void __launch_bounds__(256, 8)
mp_scatter4_kernel(const float* __restrict__ x,
                   const void* __restrict__ ei_raw,
                   float* __restrict__ out,
                   int E, int G) {
    int tid = blockIdx.x * blockDim.x + threadIdx.x;
    int g = tid >> 4;           // group of 4 consecutive edges
    int c = tid & 15;           // float4 chunk within the 64-float row
    if (g >= G) return;

    // In-kernel dtype detect: values < 50000, so an int64 layout has zero hi
    // words at odd int32 slots. 8 broadcast same-address loads, uniform
    // predicate -> no divergence, L1-resident after the first warp.
    const int* ei32 = (const int*)ei_raw;
    int hi_or = 0;
    #pragma unroll
    for (int j = 0; j < 8; j++) hi_or |= __ldg(ei32 + 2 * j + 1);
    bool is64 = (hi_or == 0);

    int e0 = g << 2;
    int n = min(4, E - e0);     // edges in this group (tail-safe)

    int dst[4], src[4];
    if (is64) {
        const long long* ei = (const long long*)ei_raw;
        #pragma unroll
        for (int k = 0; k < 4; k++) {
            int e = e0 + ((k < n) ? k : 0);
            dst[k] = (int)__ldg(ei + e);
            src[k] = (int)__ldg(ei + E + e);
        }
    } else {
        if (n == 4) {           // aligned: e0 % 4 == 0
            int4 d4 = __ldg((const int4*)(ei32 + e0));
            int4 s4 = __ldg((const int4*)(ei32 + E + e0));
            dst[0] = d4.x; dst[1] = d4.y; dst[2] = d4.z; dst[3] = d4.w;
            src[0] = s4.x; src[1] = s4.y; src[2] = s4.z; src[3] = s4.w;
        } else {
            #pragma unroll
            for (int k = 0; k < 4; k++) {
                int e = e0 + ((k < n) ? k : 0);
                dst[k] = __ldg(ei32 + e);
                src[k] = __ldg(ei32 + E + e);
            }
        }
    }

    // Phase 2: all 4 gathers in flight before any RED (asm memory clobber
    // would otherwise serialize load->red pairs).
    float4 v[4];
    #pragma unroll
    for (int k = 0; k < 4; k++)
        v[k] = __ldg((const float4*)(x + (size_t)src[k] * 64) + c);

    // Phase 3: fire-and-forget reductions.
    #pragma unroll
    for (int k = 0; k < 4; k++)
        if (k < n) red_v4(out, dst[k], c, v[k]);
}

extern "C" void kernel_launch(void* const* d_in, const int* in_sizes, int n_in,
                              void* d_out, int out_size) {
    const float* x = (const float*)d_in[0];
    const void* ei = d_in[1];
    float* out = (float*)d_out;

    int E = in_sizes[1] / 2;            // edge_index is [2, E]
    int G = (E + 3) / 4;                // groups of 4 edges

    cudaMemsetAsync(d_out, 0, (size_t)out_size * sizeof(float), 0);

    long long total = (long long)G * 16;
    int tb = 256;
    int blocks = (int)((total + tb - 1) / tb);
    mp_scatter4_kernel<<<blocks, tb>>>(x, ei, out, E, G);
}

// round 13
// speedup vs baseline: 1.0135x; 1.0135x over previous
#include <cuda_runtime.h>
#include <cstdint>

// Scatter-add message passing: out[dst] += x[src]
// x: [N, 64] fp32; edge_index: [2, E] int32.
//
// R13: minimal lock-in of all measured-best pieces.
//  - int32 indices HARDCODED: R1 proved the buffer is int32 (int64 casts gave
//    rel_err 4.7; int32 passed 8 rounds at ~6e-8). Dtype is static per
//    problem; the runtime detect cost 1.2us of kernel time (R12 vs R8).
//  - R4/R8 body: 16 lanes per group of 4 edges, lane c owns float4 chunk c.
//    int4 index loads -> 4 independent __ldg gathers (x rows have ~16x mean
//    reuse; .cg regressed 1.8us in R11) -> 4 fire-and-forget v4 REDs.
//    MLP=4 / regs 28 / full occupancy (MLP=8 and persistent-grid both
//    regressed: R6, R10).
//  - wrapper: cudaMemsetAsync zero + ONE kernel launch (leanest gap, R12).

__device__ __forceinline__ void red_v4(float* out, int dst, int c, float4 v) {
    float4* op = (float4*)(out + (size_t)dst * 64) + c;
    asm volatile("red.global.add.v4.f32 [%0], {%1, %2, %3, %4};"
                 :: "l"(op), "f"(v.x), "f"(v.y), "f"(v.z), "f"(v.w)
                 : "memory");
}

__global__ void __launch_bounds__(256, 8)
mp_scatter4_kernel(const float* __restrict__ x,
                   const int* __restrict__ ei,
                   float* __restrict__ out,
                   int E, int G) {
    int tid = blockIdx.x * blockDim.x + threadIdx.x;
    int g = tid >> 4;           // group of 4 consecutive edges
    int c = tid & 15;           // float4 chunk within the 64-float row
    if (g >= G) return;

    int e0 = g << 2;
    int n = min(4, E - e0);     // edges in this group (tail-safe)

    int dst[4], src[4];
    if (n == 4) {               // aligned: e0 % 4 == 0
        int4 d4 = __ldg((const int4*)(ei + e0));
        int4 s4 = __ldg((const int4*)(ei + E + e0));
        dst[0] = d4.x; dst[1] = d4.y; dst[2] = d4.z; dst[3] = d4.w;
        src[0] = s4.x; src[1] = s4.y; src[2] = s4.z; src[3] = s4.w;
    } else {
        #pragma unroll
        for (int k = 0; k < 4; k++) {
            int e = e0 + ((k < n) ? k : 0);
            dst[k] = __ldg(ei + e);
            src[k] = __ldg(ei + E + e);
        }
    }

    // All 4 gathers in flight before any RED (asm memory clobber would
    // otherwise serialize load->red pairs).
    float4 v[4];
    #pragma unroll
    for (int k = 0; k < 4; k++)
        v[k] = __ldg((const float4*)(x + (size_t)src[k] * 64) + c);

    // Fire-and-forget reductions.
    #pragma unroll
    for (int k = 0; k < 4; k++)
        if (k < n) red_v4(out, dst[k], c, v[k]);
}

extern "C" void kernel_launch(void* const* d_in, const int* in_sizes, int n_in,
                              void* d_out, int out_size) {
    const float* x = (const float*)d_in[0];
    const int* ei = (const int*)d_in[1];
    float* out = (float*)d_out;

    int E = in_sizes[1] / 2;            // edge_index is [2, E]
    int G = (E + 3) / 4;                // groups of 4 edges

    cudaMemsetAsync(d_out, 0, (size_t)out_size * sizeof(float), 0);

    long long total = (long long)G * 16;
    int tb = 256;
    int blocks = (int)((total + tb - 1) / tb);
    mp_scatter4_kernel<<<blocks, tb>>>(x, ei, out, E, G);
}

// round 14
// speedup vs baseline: 1.0164x; 1.0028x over previous
#include <cuda_runtime.h>
#include <cstdint>

// Scatter-add message passing: out[dst] += x[src]
// x: [N, 64] fp32; edge_index: [2, E] int32.
//
// R14 = R13 body (best kernel measured: 41.4us) + zero-KERNEL wrapper.
// Wrapper evidence: R8's zero-kernel wrapper showed a 2.4us wall-kernel gap
// vs R13's memset-node 3.7us gap at equal wall -- the driver memset node for
// a 12.8MB fill is ~1.3us slower in graph replay than a float4-store kernel.
//
// Scatter body (locked by R4/R6/R8/R10/R11/R12 sweeps):
//  - 16 lanes per group of 4 edges; lane c owns float4 chunk c.
//  - int4 index loads -> 4 independent __ldg gathers -> 4 v4 REDs.
//  - MLP=4 / regs 26 / full occupancy; int32 indices hardcoded.

__global__ void k_zero(float4* __restrict__ out, int n4) {
    int i = blockIdx.x * blockDim.x + threadIdx.x;
    if (i < n4) out[i] = make_float4(0.f, 0.f, 0.f, 0.f);
}

__device__ __forceinline__ void red_v4(float* out, int dst, int c, float4 v) {
    float4* op = (float4*)(out + (size_t)dst * 64) + c;
    asm volatile("red.global.add.v4.f32 [%0], {%1, %2, %3, %4};"
                 :: "l"(op), "f"(v.x), "f"(v.y), "f"(v.z), "f"(v.w)
                 : "memory");
}

__global__ void __launch_bounds__(256, 8)
mp_scatter4_kernel(const float* __restrict__ x,
                   const int* __restrict__ ei,
                   float* __restrict__ out,
                   int E, int G) {
    int tid = blockIdx.x * blockDim.x + threadIdx.x;
    int g = tid >> 4;           // group of 4 consecutive edges
    int c = tid & 15;           // float4 chunk within the 64-float row
    if (g >= G) return;

    int e0 = g << 2;
    int n = min(4, E - e0);     // edges in this group (tail-safe)

    int dst[4], src[4];
    if (n == 4) {               // aligned: e0 % 4 == 0
        int4 d4 = __ldg((const int4*)(ei + e0));
        int4 s4 = __ldg((const int4*)(ei + E + e0));
        dst[0] = d4.x; dst[1] = d4.y; dst[2] = d4.z; dst[3] = d4.w;
        src[0] = s4.x; src[1] = s4.y; src[2] = s4.z; src[3] = s4.w;
    } else {
        #pragma unroll
        for (int k = 0; k < 4; k++) {
            int e = e0 + ((k < n) ? k : 0);
            dst[k] = __ldg(ei + e);
            src[k] = __ldg(ei + E + e);
        }
    }

    // All 4 gathers in flight before any RED (asm memory clobber would
    // otherwise serialize load->red pairs).
    float4 v[4];
    #pragma unroll
    for (int k = 0; k < 4; k++)
        v[k] = __ldg((const float4*)(x + (size_t)src[k] * 64) + c);

    // Fire-and-forget reductions.
    #pragma unroll
    for (int k = 0; k < 4; k++)
        if (k < n) red_v4(out, dst[k], c, v[k]);
}

extern "C" void kernel_launch(void* const* d_in, const int* in_sizes, int n_in,
                              void* d_out, int out_size) {
    const float* x = (const float*)d_in[0];
    const int* ei = (const int*)d_in[1];
    float* out = (float*)d_out;

    int E = in_sizes[1] / 2;            // edge_index is [2, E]
    int G = (E + 3) / 4;                // groups of 4 edges

    int n4 = out_size / 4;              // float4 count of out
    int tb = 256;
    k_zero<<<(n4 + tb - 1) / tb, tb>>>((float4*)out, n4);

    long long total = (long long)G * 16;
    int blocks = (int)((total + tb - 1) / tb);
    mp_scatter4_kernel<<<blocks, tb>>>(x, ei, out, E, G);
}